// round 16
// baseline (speedup 1.0000x reference)
#include <cuda_runtime.h>
#include <cuda_bf16.h>
#include <math.h>
#include <stdint.h>

// ---------------- problem constants ----------------
constexpr int B_  = 16;
constexpr int D_  = 256;
constexpr int NH_ = 512;
constexpr int NV_ = 256;
constexpr int W_  = 768;
constexpr int L_  = 4;
constexpr int H_  = 8;
constexpr int A_  = 64;
constexpr int HA_ = 512;
constexpr int M_  = 512;
constexpr int R_  = 128;
constexpr int KI_KP_ = 136;
constexpr int WP_ = W_ / 2;          // 384 w-pairs
constexpr float EPS_   = 1e-5f;
constexpr float SCALE_ = 0.125f;

// ---------------- device scratch ----------------
__device__ __align__(16) uint2 g_kiP  [(size_t)B_ * W_ * KI_KP_];
__device__ __align__(16) uint2 g_kvwP [(size_t)KI_KP_ * 4096];
__device__ float g_kvb  [4096];
__device__ __align__(16) uint2 g_predP[(size_t)B_ * NV_ * (D_ / 2)];
__device__ __align__(16) uint2 g_dswP [(D_ / 2) * HA_];
__device__ __align__(16) uint2 g_dewP [(HA_ / 2) * R_];
__device__ __align__(16) uint2 g_ffw1P[(size_t)L_ * (HA_ / 2) * M_];
__device__ __align__(16) uint2 g_ffw2P[(size_t)L_ * (M_ / 2) * M_];
__device__ __align__(16) uint2 g_ffw3P[(size_t)L_ * (M_ / 2) * HA_];
__device__ __align__(16) uint2 g_kP   [(size_t)B_ * W_ * 1024];      // keys packed [b,w,kp]
__device__ __align__(16) uint2 g_vT   [(size_t)B_ * 2048 * WP_];     // vals transposed [b,j,wp]
__device__ float g_att  [B_ * NV_ * HA_];
__device__ __align__(16) uint2 g_attP [(size_t)B_ * NV_ * (HA_ / 2)];
__device__ float g_res  [B_ * NV_ * HA_];
__device__ __align__(16) uint2 g_ff1P [(size_t)B_ * NV_ * (M_ / 2)];
__device__ __align__(16) uint2 g_ff2P [(size_t)B_ * NV_ * (M_ / 2)];
__device__ float g_logits[B_ * NV_ * R_];

// ---------------- bf16 split helpers ----------------
__device__ __forceinline__ uint2 split_bf16_pair(float x0, float x1) {
    __nv_bfloat162 h = __floats2bfloat162_rn(x0, x1);
    float2 hf = __bfloat1622float2(h);
    __nv_bfloat162 l = __floats2bfloat162_rn(x0 - hf.x, x1 - hf.y);
    uint2 r;
    r.x = *reinterpret_cast<uint32_t*>(&h);
    r.y = *reinterpret_cast<uint32_t*>(&l);
    return r;
}

__device__ __forceinline__ void mma_bf16(float (&d)[4], const uint32_t (&a)[4],
                                         const uint32_t (&b)[2]) {
    asm volatile(
        "mma.sync.aligned.m16n8k16.row.col.f32.bf16.bf16.f32 "
        "{%0,%1,%2,%3},{%4,%5,%6,%7},{%8,%9},{%0,%1,%2,%3};"
        : "+f"(d[0]), "+f"(d[1]), "+f"(d[2]), "+f"(d[3])
        : "r"(a[0]), "r"(a[1]), "r"(a[2]), "r"(a[3]), "r"(b[0]), "r"(b[1]));
}

__device__ __forceinline__ void cp16(uint2* dst, const uint2* src) {
    uint32_t d = (uint32_t)__cvta_generic_to_shared(dst);
    asm volatile("cp.async.cg.shared.global [%0], [%1], 16;" :: "r"(d), "l"(src) : "memory");
}
#define CP_COMMIT() asm volatile("cp.async.commit_group;" ::: "memory")
#define CP_WAIT1()  asm volatile("cp.async.wait_group 1;" ::: "memory")
#define CP_WAIT0()  asm volatile("cp.async.wait_group 0;" ::: "memory")

// ---------------- ONE merged prep kernel (segment dispatch) ----------------
constexpr int PP_S0 = B_ * W_ * KI_KP_;           // ki packed        1671168
constexpr int PP_S1 = KI_KP_ * 4096;              // kv weights        557056
constexpr int PP_S2 = 4096;                       // kv bias
constexpr int PP_S3 = B_ * NV_ * (D_ / 2);        // predP             524288
constexpr int PP_S4 = (D_ / 2) * HA_;             // dsw
constexpr int PP_S5 = (HA_ / 2) * R_;             // dew
constexpr int PP_S6 = L_ * (HA_ / 2) * M_;        // ffw1
constexpr int PP_S7 = L_ * (M_ / 2) * M_;         // ffw2
constexpr int PP_S8 = L_ * (M_ / 2) * HA_;        // ffw3
constexpr int PP_TOTAL = PP_S0 + PP_S1 + PP_S2 + PP_S3 + PP_S4 + PP_S5 + PP_S6 + PP_S7 + PP_S8;

__global__ void prep_all(const float* __restrict__ hist, const float* __restrict__ hu,
                         const float* __restrict__ pred, const float* __restrict__ pu,
                         const float* __restrict__ kw, const float* __restrict__ vw,
                         const float* __restrict__ kb, const float* __restrict__ vb,
                         const float* __restrict__ dsw, const float* __restrict__ dew,
                         const float* __restrict__ ff1, const float* __restrict__ ff2,
                         const float* __restrict__ ff3) {
    int idx = blockIdx.x * blockDim.x + threadIdx.x;
    if (idx >= PP_TOTAL) return;
    int rem = idx;
    if (rem < PP_S0) {
        int kp = rem % KI_KP_;
        int w = (rem / KI_KP_) % W_;
        int b = rem / (KI_KP_ * W_);
        auto fetch = [&](int d) -> float {
            if (d < D_)
                return (w < NH_) ? hist[((size_t)(b * NH_ + w)) * D_ + d]
                                 : pred[((size_t)(b * NV_ + (w - NH_))) * D_ + d];
            if (d == D_)
                return (w < NH_) ? hu[b * NH_ + w] : pu[b * NV_ + (w - NH_)];
            return 0.f;
        };
        g_kiP[rem] = split_bf16_pair(fetch(2 * kp), fetch(2 * kp + 1));
        return;
    }
    rem -= PP_S0;
    if (rem < PP_S1) {
        int c = rem % 4096;
        int kp = rem / 4096;
        const float* w = (c < 2048) ? kw : vw;
        int g = (c & 2047) >> 6;
        int a = c & 63;
        auto fetch = [&](int d) -> float {
            return (d < D_ + 1) ? w[((size_t)(g * (D_ + 1) + d)) * A_ + a] : 0.f;
        };
        g_kvwP[rem] = split_bf16_pair(fetch(2 * kp), fetch(2 * kp + 1));
        return;
    }
    rem -= PP_S1;
    if (rem < PP_S2) {
        g_kvb[rem] = (rem < 2048) ? kb[rem] : vb[rem - 2048];
        return;
    }
    rem -= PP_S2;
    if (rem < PP_S3) {
        int m = rem / (D_ / 2), p = rem % (D_ / 2);
        const float* r = pred + (size_t)m * D_ + 2 * p;
        g_predP[rem] = split_bf16_pair(r[0], r[1]);
        return;
    }
    rem -= PP_S3;
    const float* in;
    uint2* out;
    int N;
    if (rem < PP_S4)      { in = dsw; out = g_dswP;  N = HA_; }
    else if ((rem -= PP_S4) < PP_S5) { in = dew; out = g_dewP;  N = R_; }
    else if ((rem -= PP_S5) < PP_S6) { in = ff1; out = g_ffw1P; N = M_; }
    else if ((rem -= PP_S6) < PP_S7) { in = ff2; out = g_ffw2P; N = M_; }
    else { rem -= PP_S7; in = ff3; out = g_ffw3P; N = HA_; }
    int kp = rem / N, n = rem % N;
    out[rem] = split_bf16_pair(in[(size_t)(2 * kp) * N + n], in[(size_t)(2 * kp + 1) * N + n]);
}

// ======================================================================
// Tensor-core GEMM, 3xBF16 split, cp.async 3-stage pipeline. (R15 engine)
// ======================================================================
template <int BM, bool RELU, bool OUTSPLIT, bool TRANSV>
__global__ __launch_bounds__(128, 4)
void gemm_tc(const uint2* __restrict__ A, const uint2* __restrict__ Bm,
             const float* __restrict__ bias, void* __restrict__ Cout,
             uint2* __restrict__ CoutP2, int ldc2,
             int KT, int ldaP, int ldb, int ldc)
{
    constexpr int MT   = BM / 32;
    constexpr int ASTR = 12;
    constexpr int ASZ  = BM * ASTR;
    constexpr int BSZ  = 8 * 68;
    constexpr int ACP  = (BM == 128) ? 4 : 2;

    extern __shared__ uint2 sm[];
    uint2* As = sm;
    uint2* Bs = sm + 3 * ASZ;

    const int bm = blockIdx.y * BM;
    const int bn = blockIdx.x * 64;
    const int t = threadIdx.x;
    const int lane = t & 31, warp = t >> 5;
    const int wm = (warp >> 1) * (BM / 2);
    const int wn = (warp & 1) * 32;
    const int fc = lane & 3, fg = lane >> 2;

    const int arow = (BM == 128) ? t : (t >> 1);
    const int akp  = (BM == 128) ? 0 : (t & 1) * 4;
    const int bkN = t >> 4, bnN = (t & 15) * 4;

    auto issue = [&](int kt, int s) {
        const uint2* asrc = A + (size_t)(bm + arow) * ldaP + kt * 8 + akp;
        uint2* adst = As + s * ASZ + arow * ASTR + akp;
#pragma unroll
        for (int q = 0; q < ACP; q++) cp16(adst + 2 * q, asrc + 2 * q);
        const uint2* bsrc = Bm + (size_t)(kt * 8 + bkN) * ldb + bn + bnN;
        uint2* bdst = Bs + s * BSZ + bkN * 68 + bnN;
        cp16(bdst, bsrc);
        cp16(bdst + 2, bsrc + 2);
    };

    float acc[MT][4][4] = {};

    issue(0, 0);
    CP_COMMIT();
    issue(1, 1);
    CP_COMMIT();
    CP_WAIT1();
    __syncthreads();

    for (int kt = 0; kt < KT; kt++) {
        const int p = kt % 3;
        const uint2* Ab = As + p * ASZ;
        const uint2* Bb = Bs + p * BSZ;

        uint32_t bh[4][2], bl[4][2];
#pragma unroll
        for (int nt = 0; nt < 4; nt++) {
            int nb = wn + nt * 8 + fg;
            uint2 v0 = Bb[fc * 68 + nb];
            uint2 v1 = Bb[(fc + 4) * 68 + nb];
            bh[nt][0] = v0.x; bl[nt][0] = v0.y;
            bh[nt][1] = v1.x; bl[nt][1] = v1.y;
        }
#pragma unroll
        for (int mt = 0; mt < MT; mt++) {
            int mr = wm + mt * 16 + fg;
            uint2 v0 = Ab[mr * ASTR + fc];
            uint2 v1 = Ab[(mr + 8) * ASTR + fc];
            uint2 v2 = Ab[mr * ASTR + fc + 4];
            uint2 v3 = Ab[(mr + 8) * ASTR + fc + 4];
            uint32_t ah[4] = {v0.x, v1.x, v2.x, v3.x};
            uint32_t al[4] = {v0.y, v1.y, v2.y, v3.y};
#pragma unroll
            for (int nt = 0; nt < 4; nt++) {
                mma_bf16(acc[mt][nt], ah, bh[nt]);
                mma_bf16(acc[mt][nt], ah, bl[nt]);
                mma_bf16(acc[mt][nt], al, bh[nt]);
            }
        }

        if (kt + 2 < KT) issue(kt + 2, (kt + 2) % 3);
        CP_COMMIT();
        CP_WAIT1();
        __syncthreads();
    }

#pragma unroll
    for (int mt = 0; mt < MT; mt++) {
#pragma unroll
        for (int nt = 0; nt < 4; nt++) {
            int n0 = bn + wn + nt * 8 + fc * 2;
#pragma unroll
            for (int half = 0; half < 2; half++) {
                int m = bm + wm + mt * 16 + fg + half * 8;
                float v0 = acc[mt][nt][half * 2] + bias[n0];
                float v1 = acc[mt][nt][half * 2 + 1] + bias[n0 + 1];
                if (RELU) { v0 = fmaxf(v0, 0.f); v1 = fmaxf(v1, 0.f); }
                if (TRANSV) {
                    float p0 = __shfl_xor_sync(0xffffffffu, v0, 4);
                    float p1 = __shfl_xor_sync(0xffffffffu, v1, 4);
                    if (n0 < 2048) {
                        ((uint2*)Cout)[(size_t)m * ldc + (n0 >> 1)] = split_bf16_pair(v0, v1);
                    } else if ((fg & 1) == 0) {
                        int bb = m / W_;
                        int wp = (m % W_) >> 1;
                        size_t base = ((size_t)bb * 2048 + (n0 - 2048)) * WP_ + wp;
                        CoutP2[base]       = split_bf16_pair(v0, p0);
                        CoutP2[base + WP_] = split_bf16_pair(v1, p1);
                    }
                } else if (OUTSPLIT) {
                    ((uint2*)Cout)[(size_t)m * ldc + (n0 >> 1)] = split_bf16_pair(v0, v1);
                } else {
                    *(float2*)((float*)Cout + (size_t)m * ldc + n0) = make_float2(v0, v1);
                    if (CoutP2)
                        CoutP2[(size_t)m * ldc2 + (n0 >> 1)] = split_bf16_pair(v0, v1);
                }
            }
        }
    }
}

// ======================================================================
// Fused flash attention v5: K single-buffered, V double-buffered ->
// smem 55.3KB -> 4 CTAs/SM -> single wave (512 CTAs on 592 slots).
// K(wt+1)/V(wt+1) issued after post-scores barrier; latency hides
// under softmax+PV.
// ======================================================================
constexpr int FA_TSZ  = 64 * 36;
constexpr int FA_SMEM = 3 * FA_TSZ * 8;   // 55296

__global__ __launch_bounds__(128, 4)
void fa_kernel(const uint2* __restrict__ QPg, const float* __restrict__ Qf,
               const uint2* __restrict__ Kg, const uint2* __restrict__ Vt,
               float* __restrict__ Rg, int l)
{
    const int vt = blockIdx.x;
    const int bh = blockIdx.y;
    const int b = bh >> 3, h = bh & 7;
    const int t = threadIdx.x;
    const int lane = t & 31, warp = t >> 5;
    const int wm = warp * 16;
    const int fc = lane & 3, fg = lane >> 2;

    extern __shared__ uint2 smu[];
    uint2* Ks = smu;                      // [64][36] single buffer
    uint2* Vs = smu + FA_TSZ;             // [2][64][36]

    const float* qbase = Qf + ((size_t)(b * NV_ + vt * 64)) * HA_ + h * A_;
    const uint2* kbase = Kg + (size_t)(b * W_) * 1024 + (l * H_ + h) * 32;
    const uint2* vbase = Vt + ((size_t)b * 2048 + (l * H_ + h) * 64) * WP_;

    uint32_t qh[4][4], ql[4][4];
    {
        const uint2* qp = QPg + (size_t)(b * NV_ + vt * 64) * (HA_ / 2) + h * 32;
        const size_t r0 = (size_t)(wm + fg) * (HA_ / 2);
        const size_t r1 = (size_t)(wm + fg + 8) * (HA_ / 2);
#pragma unroll
        for (int kc = 0; kc < 4; kc++) {
            uint2 q0 = qp[r0 + kc * 8 + fc];
            uint2 q1 = qp[r1 + kc * 8 + fc];
            uint2 q2 = qp[r0 + kc * 8 + fc + 4];
            uint2 q3 = qp[r1 + kc * 8 + fc + 4];
            qh[kc][0] = q0.x; qh[kc][1] = q1.x; qh[kc][2] = q2.x; qh[kc][3] = q3.x;
            ql[kc][0] = q0.y; ql[kc][1] = q1.y; ql[kc][2] = q2.y; ql[kc][3] = q3.y;
        }
    }

    const int lr = t >> 1, lh = (t & 1) * 16;
    auto issueK = [&](int wt) {
        const uint2* ksrc = kbase + (size_t)(wt * 64 + lr) * 1024 + lh;
        uint2* kdst = Ks + lr * 36 + lh;
#pragma unroll
        for (int q = 0; q < 8; q++) cp16(kdst + 2 * q, ksrc + 2 * q);
    };
    auto issueV = [&](int wt, int s) {
        const uint2* vsrc = vbase + (size_t)lr * WP_ + wt * 32 + (t & 1) * 16;
        uint2* vdst = Vs + s * FA_TSZ + lr * 36 + (t & 1) * 16;
#pragma unroll
        for (int q = 0; q < 8; q++) cp16(vdst + 2 * q, vsrc + 2 * q);
    };

    float O[8][4] = {};
    float s_m[2] = {-INFINITY, -INFINITY};
    float s_l[2] = {0.f, 0.f};

    const int ntiles = vt + 9;
    issueK(0);
    issueV(0, 0);
    CP_COMMIT();

    for (int wt = 0; wt < ntiles; wt++) {
        CP_WAIT0();
        __syncthreads();          // K(wt), V(wt) visible; prior PV reads done

        // scores from Ks
        float s[8][4] = {};
#pragma unroll
        for (int kc = 0; kc < 4; kc++) {
#pragma unroll
            for (int nt = 0; nt < 8; nt++) {
                int nc = nt * 8 + fg;
                uint2 k0 = Ks[nc * 36 + kc * 8 + fc];
                uint2 k1 = Ks[nc * 36 + kc * 8 + fc + 4];
                uint32_t bhv[2] = {k0.x, k1.x}, blv[2] = {k0.y, k1.y};
                mma_bf16(s[nt], qh[kc], bhv);
                mma_bf16(s[nt], qh[kc], blv);
                mma_bf16(s[nt], ql[kc], bhv);
            }
        }
        __syncthreads();          // all warps done reading Ks
        if (wt + 1 < ntiles) {
            issueK(wt + 1);
            issueV(wt + 1, (wt + 1) & 1);
            CP_COMMIT();
        }

        // softmax (registers + quad shfl)
        const bool mtile = (wt == vt + 8);
        float mx[2] = {-INFINITY, -INFINITY};
#pragma unroll
        for (int nt = 0; nt < 8; nt++)
#pragma unroll
            for (int c = 0; c < 4; c++) {
                float v = s[nt][c] * SCALE_;
                if (mtile) {
                    int wg = wt * 64 + nt * 8 + fc * 2 + (c & 1);
                    int vg = vt * 64 + wm + fg + (c >> 1) * 8;
                    if (wg >= NH_ + vg) v = -INFINITY;
                }
                s[nt][c] = v;
                mx[c >> 1] = fmaxf(mx[c >> 1], v);
            }
#pragma unroll
        for (int i = 0; i < 2; i++) {
            mx[i] = fmaxf(mx[i], __shfl_xor_sync(0xffffffffu, mx[i], 1));
            mx[i] = fmaxf(mx[i], __shfl_xor_sync(0xffffffffu, mx[i], 2));
        }

        float mnew[2], alpha[2], sum[2];
#pragma unroll
        for (int i = 0; i < 2; i++) {
            mnew[i] = fmaxf(s_m[i], mx[i]);
            alpha[i] = __expf(s_m[i] - mnew[i]);
            s_m[i] = mnew[i];
            sum[i] = 0.f;
        }
#pragma unroll
        for (int nt = 0; nt < 8; nt++)
#pragma unroll
            for (int c = 0; c < 4; c++) {
                float p = __expf(s[nt][c] - mnew[c >> 1]);
                s[nt][c] = p;
                sum[c >> 1] += p;
            }
#pragma unroll
        for (int i = 0; i < 2; i++) {
            sum[i] += __shfl_xor_sync(0xffffffffu, sum[i], 1);
            sum[i] += __shfl_xor_sync(0xffffffffu, sum[i], 2);
            s_l[i] = s_l[i] * alpha[i] + sum[i];
        }

#pragma unroll
        for (int ntj = 0; ntj < 8; ntj++)
#pragma unroll
            for (int c = 0; c < 4; c++)
                O[ntj][c] *= alpha[c >> 1];

        // PV from Vs[wt&1]
        const uint2* Vb = Vs + (wt & 1) * FA_TSZ;
#pragma unroll
        for (int kc = 0; kc < 4; kc++) {
            uint2 u;
            uint32_t ph[4], pl[4];
            u = split_bf16_pair(s[2 * kc][0], s[2 * kc][1]);         ph[0] = u.x; pl[0] = u.y;
            u = split_bf16_pair(s[2 * kc][2], s[2 * kc][3]);         ph[1] = u.x; pl[1] = u.y;
            u = split_bf16_pair(s[2 * kc + 1][0], s[2 * kc + 1][1]); ph[2] = u.x; pl[2] = u.y;
            u = split_bf16_pair(s[2 * kc + 1][2], s[2 * kc + 1][3]); ph[3] = u.x; pl[3] = u.y;
#pragma unroll
            for (int ntj = 0; ntj < 8; ntj++) {
                int nc = ntj * 8 + fg;
                uint2 v0 = Vb[nc * 36 + kc * 8 + fc];
                uint2 v1 = Vb[nc * 36 + kc * 8 + fc + 4];
                uint32_t bhv[2] = {v0.x, v1.x}, blv[2] = {v0.y, v1.y};
                mma_bf16(O[ntj], ph, bhv);
                mma_bf16(O[ntj], ph, blv);
                mma_bf16(O[ntj], pl, bhv);
            }
        }
    }

    float linv[2] = {1.f / s_l[0], 1.f / s_l[1]};
#pragma unroll
    for (int half = 0; half < 2; half++) {
        int row = wm + fg + half * 8;
        const float* arow = qbase + (size_t)row * HA_;
        float* orow = Rg + ((size_t)(b * NV_ + vt * 64 + row)) * HA_ + h * A_;
#pragma unroll
        for (int ntj = 0; ntj < 8; ntj++) {
            int j = ntj * 8 + fc * 2;
            float2 a = *(const float2*)(arow + j);
            float2 o;
            o.x = a.x + O[ntj][half * 2]     * linv[half];
            o.y = a.y + O[ntj][half * 2 + 1] * linv[half];
            *(float2*)(orow + j) = o;
        }
    }
}

// ---------------- layernorm: warp-per-row, shfl-only ----------------
__global__ void ln_kernel(const float* __restrict__ base, const float* __restrict__ delta,
                          const float* __restrict__ gamma, const float* __restrict__ beta,
                          float* __restrict__ out, uint2* __restrict__ outP) {
    const int warp = threadIdx.x >> 5, lane = threadIdx.x & 31;
    const int row = blockIdx.x * 8 + warp;
    const int c0 = lane * 16;
    const float* br = base + (size_t)row * HA_ + c0;
    float4 x[4];
#pragma unroll
    for (int q = 0; q < 4; q++) x[q] = *(const float4*)(br + q * 4);
    if (delta) {
        const float* dr = delta + (size_t)row * HA_ + c0;
#pragma unroll
        for (int q = 0; q < 4; q++) {
            float4 d = *(const float4*)(dr + q * 4);
            x[q].x += d.x; x[q].y += d.y; x[q].z += d.z; x[q].w += d.w;
        }
    }
    float sum = 0.f;
#pragma unroll
    for (int q = 0; q < 4; q++) sum += x[q].x + x[q].y + x[q].z + x[q].w;
#pragma unroll
    for (int o = 16; o > 0; o >>= 1) sum += __shfl_xor_sync(0xffffffffu, sum, o);
    float mean = sum * (1.f / HA_);
    float var = 0.f;
#pragma unroll
    for (int q = 0; q < 4; q++) {
        x[q].x -= mean; x[q].y -= mean; x[q].z -= mean; x[q].w -= mean;
        var += x[q].x * x[q].x + x[q].y * x[q].y + x[q].z * x[q].z + x[q].w * x[q].w;
    }
#pragma unroll
    for (int o = 16; o > 0; o >>= 1) var += __shfl_xor_sync(0xffffffffu, var, o);
    float inv = rsqrtf(var * (1.f / HA_) + EPS_);
    float* orow = out + (size_t)row * HA_ + c0;
    uint2* prow = outP + (size_t)row * (HA_ / 2) + (c0 >> 1);
#pragma unroll
    for (int q = 0; q < 4; q++) {
        float4 g = *(const float4*)(gamma + c0 + q * 4);
        float4 be = *(const float4*)(beta + c0 + q * 4);
        float4 o;
        o.x = g.x * (x[q].x * inv) + be.x;
        o.y = g.y * (x[q].y * inv) + be.y;
        o.z = g.z * (x[q].z * inv) + be.z;
        o.w = g.w * (x[q].w * inv) + be.w;
        *(float4*)(orow + q * 4) = o;
        prow[q * 2]     = split_bf16_pair(o.x, o.y);
        prow[q * 2 + 1] = split_bf16_pair(o.z, o.w);
    }
}

// ---------------- final loss reduction ----------------
__global__ void loss_kernel(const float* __restrict__ pu, float* __restrict__ out) {
    const int b = blockIdx.x;
    const int t = threadIdx.x;
    const int warp = t >> 5, lane = t & 31;
    const float LOG_R = logf((float)R_);
    float accum = 0.f;
    for (int v = 1 + warp; v < NV_; v += 8) {
        const float* lr = g_logits + ((size_t)(b * NV_ + v)) * R_;
        float lv[4];
        float m = -INFINITY;
#pragma unroll
        for (int i = 0; i < 4; i++) { lv[i] = lr[lane + i * 32]; m = fmaxf(m, lv[i]); }
#pragma unroll
        for (int o = 16; o > 0; o >>= 1) m = fmaxf(m, __shfl_xor_sync(0xffffffffu, m, o));
        float se = 0.f;
#pragma unroll
        for (int i = 0; i < 4; i++) se += expf(lv[i] - m);
#pragma unroll
        for (int o = 16; o > 0; o >>= 1) se += __shfl_xor_sync(0xffffffffu, se, o);
        if (lane == 0) {
            float lse = m + logf(se);
            int tgt = (int)floorf(pu[b * NV_ + v] * (float)R_);
            tgt = min(max(tgt, 0), R_ - 1);
            accum += lse - lr[tgt] - LOG_R;
        }
    }
    __shared__ float red[8];
    if (lane == 0) red[warp] = accum;
    __syncthreads();
    if (t == 0) {
        float s = 0.f;
#pragma unroll
        for (int i = 0; i < 8; i++) s += red[i];
        out[b] = s;
    }
}

// ---------------- host launch ----------------
template <typename T>
static T* sym_addr(const void* sym) {
    void* p = nullptr;
    cudaGetSymbolAddress(&p, sym);
    return (T*)p;
}

extern "C" void kernel_launch(void* const* d_in, const int* in_sizes, int n_in,
                              void* d_out, int out_size) {
    (void)in_sizes; (void)n_in; (void)out_size;
    const float* hist  = (const float*)d_in[0];
    const float* hu    = (const float*)d_in[1];
    const float* pred  = (const float*)d_in[2];
    const float* pu    = (const float*)d_in[3];
    const float* ds_w  = (const float*)d_in[4];
    const float* ds_b  = (const float*)d_in[5];
    const float* key_w = (const float*)d_in[6];
    const float* key_b = (const float*)d_in[7];
    const float* val_w = (const float*)d_in[8];
    const float* val_b = (const float*)d_in[9];
    const float* ln1_g = (const float*)d_in[10];
    const float* ln1_b = (const float*)d_in[11];
    const float* ln2_g = (const float*)d_in[12];
    const float* ln2_b = (const float*)d_in[13];
    const float* ff_w1 = (const float*)d_in[14];
    const float* ff_b1 = (const float*)d_in[15];
    const float* ff_w2 = (const float*)d_in[16];
    const float* ff_b2 = (const float*)d_in[17];
    const float* ff_w3 = (const float*)d_in[18];
    const float* ff_b3 = (const float*)d_in[19];
    const float* de_w  = (const float*)d_in[20];
    const float* de_b  = (const float*)d_in[21];
    float* out = (float*)d_out;

    uint2* kiP   = sym_addr<uint2>(g_kiP);
    uint2* kvwP  = sym_addr<uint2>(g_kvwP);
    float* kvb   = sym_addr<float>(g_kvb);
    uint2* predP = sym_addr<uint2>(g_predP);
    uint2* dswP  = sym_addr<uint2>(g_dswP);
    uint2* dewP  = sym_addr<uint2>(g_dewP);
    uint2* ffw1P = sym_addr<uint2>(g_ffw1P);
    uint2* ffw2P = sym_addr<uint2>(g_ffw2P);
    uint2* ffw3P = sym_addr<uint2>(g_ffw3P);
    uint2* kP    = sym_addr<uint2>(g_kP);
    uint2* vT    = sym_addr<uint2>(g_vT);
    float* att   = sym_addr<float>(g_att);
    uint2* attP  = sym_addr<uint2>(g_attP);
    float* res   = sym_addr<float>(g_res);
    uint2* ff1P  = sym_addr<uint2>(g_ff1P);
    uint2* ff2P  = sym_addr<uint2>(g_ff2P);
    float* logit = sym_addr<float>(g_logits);

    const int SM64  = 3 * (64 * 12 + 8 * 68) * 8;
    const int SM128 = 3 * (128 * 12 + 8 * 68) * 8;

    cudaFuncSetAttribute(fa_kernel, cudaFuncAttributeMaxDynamicSharedMemorySize, FA_SMEM);
    cudaFuncSetAttribute(gemm_tc<64, false, false, false>, cudaFuncAttributeMaxDynamicSharedMemorySize, SM64);
    cudaFuncSetAttribute(gemm_tc<64, true, true, false>, cudaFuncAttributeMaxDynamicSharedMemorySize, SM64);
    cudaFuncSetAttribute(gemm_tc<128, false, true, true>, cudaFuncAttributeMaxDynamicSharedMemorySize, SM128);

    const int BNV = B_ * NV_;
    const int BW  = B_ * W_;

    // ---- merged prep (1 launch) ----
    prep_all<<<(PP_TOTAL + 255) / 256, 256>>>(hist, hu, pred, pu, key_w, val_w, key_b, val_b,
                                              ds_w, de_w, ff_w1, ff_w2, ff_w3);

    // ---- ds: att = pred @ ds_w + b  (dual output: f32 + packed attP)
    gemm_tc<64, false, false, false><<<dim3(HA_ / 64, BNV / 64), 128, SM64>>>(
        predP, dswP, ds_b, att, attP, HA_ / 2, 16, D_ / 2, HA_, HA_);
    // ---- keys|vals combined; keys -> g_kP packed, vals -> g_vT transposed
    gemm_tc<128, false, true, true><<<dim3(4096 / 64, BW / 128), 128, SM128>>>(
        kiP, kvwP, kvb, kP, vT, 0, 17, KI_KP_, 4096, 1024);

    // ---- layers ----
    for (int l = 0; l < L_; l++) {
        fa_kernel<<<dim3(NV_ / 64, B_ * H_), 128, FA_SMEM>>>(attP, att, kP, vT, res, l);
        ln_kernel<<<BNV / 8, 256>>>(res, nullptr, ln1_g + l * HA_, ln1_b + l * HA_, att, attP);
        gemm_tc<64, true, true, false><<<dim3(M_ / 64, BNV / 64), 128, SM64>>>(
            attP, ffw1P + (size_t)l * (HA_ / 2) * M_, ff_b1 + l * M_, ff1P, nullptr, 0,
            32, HA_ / 2, M_, M_ / 2);
        gemm_tc<64, true, true, false><<<dim3(M_ / 64, BNV / 64), 128, SM64>>>(
            ff1P, ffw2P + (size_t)l * (M_ / 2) * M_, ff_b2 + l * M_, ff2P, nullptr, 0,
            32, M_ / 2, M_, M_ / 2);
        gemm_tc<64, false, false, false><<<dim3(HA_ / 64, BNV / 64), 128, SM64>>>(
            ff2P, ffw3P + (size_t)l * (M_ / 2) * HA_, ff_b3 + l * HA_, res, nullptr, 0,
            32, M_ / 2, HA_, HA_);
        ln_kernel<<<BNV / 8, 256>>>(att, res, ln2_g + l * HA_, ln2_b + l * HA_, att, attP);
    }
    // ---- logits + loss ----
    gemm_tc<64, false, false, false><<<dim3(R_ / 64, BNV / 64), 128, SM64>>>(
        attP, dewP, de_b, logit, nullptr, 0, 32, HA_ / 2, R_, R_);
    loss_kernel<<<B_, 256>>>(pu, out);
}

// round 17
// speedup vs baseline: 1.0559x; 1.0559x over previous
#include <cuda_runtime.h>
#include <cuda_bf16.h>
#include <math.h>
#include <stdint.h>

// ---------------- problem constants ----------------
constexpr int B_  = 16;
constexpr int D_  = 256;
constexpr int NH_ = 512;
constexpr int NV_ = 256;
constexpr int W_  = 768;
constexpr int L_  = 4;
constexpr int H_  = 8;
constexpr int A_  = 64;
constexpr int HA_ = 512;
constexpr int M_  = 512;
constexpr int R_  = 128;
constexpr int KI_KP_ = 136;
constexpr int WP_ = W_ / 2;          // 384 w-pairs
constexpr float EPS_   = 1e-5f;
constexpr float SCALE_ = 0.125f;

// ---------------- device scratch ----------------
__device__ __align__(16) uint2 g_kiP  [(size_t)B_ * W_ * KI_KP_];
__device__ __align__(16) uint2 g_kvwP [(size_t)KI_KP_ * 4096];
__device__ float g_kvb  [4096];
__device__ __align__(16) uint2 g_predP[(size_t)B_ * NV_ * (D_ / 2)];
__device__ __align__(16) uint2 g_dswP [(D_ / 2) * HA_];
__device__ __align__(16) uint2 g_dewP [(HA_ / 2) * R_];
__device__ __align__(16) uint2 g_ffw1P[(size_t)L_ * (HA_ / 2) * M_];
__device__ __align__(16) uint2 g_ffw2P[(size_t)L_ * (M_ / 2) * M_];
__device__ __align__(16) uint2 g_ffw3P[(size_t)L_ * (M_ / 2) * HA_];
__device__ __align__(16) uint2 g_kP   [(size_t)B_ * W_ * 1024];      // keys packed [b,w,kp]
__device__ __align__(16) uint2 g_vT   [(size_t)B_ * 2048 * WP_];     // vals transposed [b,j,wp]
__device__ float g_att  [B_ * NV_ * HA_];
__device__ __align__(16) uint2 g_attP [(size_t)B_ * NV_ * (HA_ / 2)];
__device__ float g_res  [B_ * NV_ * HA_];
__device__ __align__(16) uint2 g_ff1P [(size_t)B_ * NV_ * (M_ / 2)];
__device__ __align__(16) uint2 g_ff2P [(size_t)B_ * NV_ * (M_ / 2)];
__device__ float g_logits[B_ * NV_ * R_];

// ---------------- bf16 split helpers ----------------
__device__ __forceinline__ uint2 split_bf16_pair(float x0, float x1) {
    __nv_bfloat162 h = __floats2bfloat162_rn(x0, x1);
    float2 hf = __bfloat1622float2(h);
    __nv_bfloat162 l = __floats2bfloat162_rn(x0 - hf.x, x1 - hf.y);
    uint2 r;
    r.x = *reinterpret_cast<uint32_t*>(&h);
    r.y = *reinterpret_cast<uint32_t*>(&l);
    return r;
}

__device__ __forceinline__ void mma_bf16(float (&d)[4], const uint32_t (&a)[4],
                                         const uint32_t (&b)[2]) {
    asm volatile(
        "mma.sync.aligned.m16n8k16.row.col.f32.bf16.bf16.f32 "
        "{%0,%1,%2,%3},{%4,%5,%6,%7},{%8,%9},{%0,%1,%2,%3};"
        : "+f"(d[0]), "+f"(d[1]), "+f"(d[2]), "+f"(d[3])
        : "r"(a[0]), "r"(a[1]), "r"(a[2]), "r"(a[3]), "r"(b[0]), "r"(b[1]));
}

__device__ __forceinline__ void cp16(uint2* dst, const uint2* src) {
    uint32_t d = (uint32_t)__cvta_generic_to_shared(dst);
    asm volatile("cp.async.cg.shared.global [%0], [%1], 16;" :: "r"(d), "l"(src) : "memory");
}
#define CP_COMMIT() asm volatile("cp.async.commit_group;" ::: "memory")
#define CP_WAIT1()  asm volatile("cp.async.wait_group 1;" ::: "memory")
#define CP_WAIT0()  asm volatile("cp.async.wait_group 0;" ::: "memory")

// ---------------- ONE merged prep kernel (segment dispatch) ----------------
constexpr int PP_S0 = B_ * W_ * KI_KP_;
constexpr int PP_S1 = KI_KP_ * 4096;
constexpr int PP_S2 = 4096;
constexpr int PP_S3 = B_ * NV_ * (D_ / 2);
constexpr int PP_S4 = (D_ / 2) * HA_;
constexpr int PP_S5 = (HA_ / 2) * R_;
constexpr int PP_S6 = L_ * (HA_ / 2) * M_;
constexpr int PP_S7 = L_ * (M_ / 2) * M_;
constexpr int PP_S8 = L_ * (M_ / 2) * HA_;
constexpr int PP_TOTAL = PP_S0 + PP_S1 + PP_S2 + PP_S3 + PP_S4 + PP_S5 + PP_S6 + PP_S7 + PP_S8;

__global__ void prep_all(const float* __restrict__ hist, const float* __restrict__ hu,
                         const float* __restrict__ pred, const float* __restrict__ pu,
                         const float* __restrict__ kw, const float* __restrict__ vw,
                         const float* __restrict__ kb, const float* __restrict__ vb,
                         const float* __restrict__ dsw, const float* __restrict__ dew,
                         const float* __restrict__ ff1, const float* __restrict__ ff2,
                         const float* __restrict__ ff3) {
    int idx = blockIdx.x * blockDim.x + threadIdx.x;
    if (idx >= PP_TOTAL) return;
    int rem = idx;
    if (rem < PP_S0) {
        int kp = rem % KI_KP_;
        int w = (rem / KI_KP_) % W_;
        int b = rem / (KI_KP_ * W_);
        auto fetch = [&](int d) -> float {
            if (d < D_)
                return (w < NH_) ? hist[((size_t)(b * NH_ + w)) * D_ + d]
                                 : pred[((size_t)(b * NV_ + (w - NH_))) * D_ + d];
            if (d == D_)
                return (w < NH_) ? hu[b * NH_ + w] : pu[b * NV_ + (w - NH_)];
            return 0.f;
        };
        g_kiP[rem] = split_bf16_pair(fetch(2 * kp), fetch(2 * kp + 1));
        return;
    }
    rem -= PP_S0;
    if (rem < PP_S1) {
        int c = rem % 4096;
        int kp = rem / 4096;
        const float* w = (c < 2048) ? kw : vw;
        int g = (c & 2047) >> 6;
        int a = c & 63;
        auto fetch = [&](int d) -> float {
            return (d < D_ + 1) ? w[((size_t)(g * (D_ + 1) + d)) * A_ + a] : 0.f;
        };
        g_kvwP[rem] = split_bf16_pair(fetch(2 * kp), fetch(2 * kp + 1));
        return;
    }
    rem -= PP_S1;
    if (rem < PP_S2) {
        g_kvb[rem] = (rem < 2048) ? kb[rem] : vb[rem - 2048];
        return;
    }
    rem -= PP_S2;
    if (rem < PP_S3) {
        int m = rem / (D_ / 2), p = rem % (D_ / 2);
        const float* r = pred + (size_t)m * D_ + 2 * p;
        g_predP[rem] = split_bf16_pair(r[0], r[1]);
        return;
    }
    rem -= PP_S3;
    const float* in;
    uint2* out;
    int N;
    if (rem < PP_S4)      { in = dsw; out = g_dswP;  N = HA_; }
    else if ((rem -= PP_S4) < PP_S5) { in = dew; out = g_dewP;  N = R_; }
    else if ((rem -= PP_S5) < PP_S6) { in = ff1; out = g_ffw1P; N = M_; }
    else if ((rem -= PP_S6) < PP_S7) { in = ff2; out = g_ffw2P; N = M_; }
    else { rem -= PP_S7; in = ff3; out = g_ffw3P; N = HA_; }
    int kp = rem / N, n = rem % N;
    out[rem] = split_bf16_pair(in[(size_t)(2 * kp) * N + n], in[(size_t)(2 * kp + 1) * N + n]);
}

// ======================================================================
// Tensor-core GEMM, 3xBF16 split, cp.async 3-stage pipeline.
// ======================================================================
template <int BM, bool RELU, bool OUTSPLIT, bool TRANSV>
__global__ __launch_bounds__(128, 4)
void gemm_tc(const uint2* __restrict__ A, const uint2* __restrict__ Bm,
             const float* __restrict__ bias, void* __restrict__ Cout,
             uint2* __restrict__ CoutP2, int ldc2,
             int KT, int ldaP, int ldb, int ldc)
{
    constexpr int MT   = BM / 32;
    constexpr int ASTR = 12;
    constexpr int ASZ  = BM * ASTR;
    constexpr int BSZ  = 8 * 68;
    constexpr int ACP  = (BM == 128) ? 4 : 2;

    extern __shared__ uint2 sm[];
    uint2* As = sm;
    uint2* Bs = sm + 3 * ASZ;

    const int bm = blockIdx.y * BM;
    const int bn = blockIdx.x * 64;
    const int t = threadIdx.x;
    const int lane = t & 31, warp = t >> 5;
    const int wm = (warp >> 1) * (BM / 2);
    const int wn = (warp & 1) * 32;
    const int fc = lane & 3, fg = lane >> 2;

    const int arow = (BM == 128) ? t : (t >> 1);
    const int akp  = (BM == 128) ? 0 : (t & 1) * 4;
    const int bkN = t >> 4, bnN = (t & 15) * 4;

    auto issue = [&](int kt, int s) {
        const uint2* asrc = A + (size_t)(bm + arow) * ldaP + kt * 8 + akp;
        uint2* adst = As + s * ASZ + arow * ASTR + akp;
#pragma unroll
        for (int q = 0; q < ACP; q++) cp16(adst + 2 * q, asrc + 2 * q);
        const uint2* bsrc = Bm + (size_t)(kt * 8 + bkN) * ldb + bn + bnN;
        uint2* bdst = Bs + s * BSZ + bkN * 68 + bnN;
        cp16(bdst, bsrc);
        cp16(bdst + 2, bsrc + 2);
    };

    float acc[MT][4][4] = {};

    issue(0, 0);
    CP_COMMIT();
    issue(1, 1);
    CP_COMMIT();
    CP_WAIT1();
    __syncthreads();

    for (int kt = 0; kt < KT; kt++) {
        const int p = kt % 3;
        const uint2* Ab = As + p * ASZ;
        const uint2* Bb = Bs + p * BSZ;

        uint32_t bh[4][2], bl[4][2];
#pragma unroll
        for (int nt = 0; nt < 4; nt++) {
            int nb = wn + nt * 8 + fg;
            uint2 v0 = Bb[fc * 68 + nb];
            uint2 v1 = Bb[(fc + 4) * 68 + nb];
            bh[nt][0] = v0.x; bl[nt][0] = v0.y;
            bh[nt][1] = v1.x; bl[nt][1] = v1.y;
        }
#pragma unroll
        for (int mt = 0; mt < MT; mt++) {
            int mr = wm + mt * 16 + fg;
            uint2 v0 = Ab[mr * ASTR + fc];
            uint2 v1 = Ab[(mr + 8) * ASTR + fc];
            uint2 v2 = Ab[mr * ASTR + fc + 4];
            uint2 v3 = Ab[(mr + 8) * ASTR + fc + 4];
            uint32_t ah[4] = {v0.x, v1.x, v2.x, v3.x};
            uint32_t al[4] = {v0.y, v1.y, v2.y, v3.y};
#pragma unroll
            for (int nt = 0; nt < 4; nt++) {
                mma_bf16(acc[mt][nt], ah, bh[nt]);
                mma_bf16(acc[mt][nt], ah, bl[nt]);
                mma_bf16(acc[mt][nt], al, bh[nt]);
            }
        }

        if (kt + 2 < KT) issue(kt + 2, (kt + 2) % 3);
        CP_COMMIT();
        CP_WAIT1();
        __syncthreads();
    }

#pragma unroll
    for (int mt = 0; mt < MT; mt++) {
#pragma unroll
        for (int nt = 0; nt < 4; nt++) {
            int n0 = bn + wn + nt * 8 + fc * 2;
#pragma unroll
            for (int half = 0; half < 2; half++) {
                int m = bm + wm + mt * 16 + fg + half * 8;
                float v0 = acc[mt][nt][half * 2] + bias[n0];
                float v1 = acc[mt][nt][half * 2 + 1] + bias[n0 + 1];
                if (RELU) { v0 = fmaxf(v0, 0.f); v1 = fmaxf(v1, 0.f); }
                if (TRANSV) {
                    float p0 = __shfl_xor_sync(0xffffffffu, v0, 4);
                    float p1 = __shfl_xor_sync(0xffffffffu, v1, 4);
                    if (n0 < 2048) {
                        ((uint2*)Cout)[(size_t)m * ldc + (n0 >> 1)] = split_bf16_pair(v0, v1);
                    } else if ((fg & 1) == 0) {
                        int bb = m / W_;
                        int wp = (m % W_) >> 1;
                        size_t base = ((size_t)bb * 2048 + (n0 - 2048)) * WP_ + wp;
                        CoutP2[base]       = split_bf16_pair(v0, p0);
                        CoutP2[base + WP_] = split_bf16_pair(v1, p1);
                    }
                } else if (OUTSPLIT) {
                    ((uint2*)Cout)[(size_t)m * ldc + (n0 >> 1)] = split_bf16_pair(v0, v1);
                } else {
                    *(float2*)((float*)Cout + (size_t)m * ldc + n0) = make_float2(v0, v1);
                    if (CoutP2)
                        CoutP2[(size_t)m * ldc2 + (n0 >> 1)] = split_bf16_pair(v0, v1);
                }
            }
        }
    }
}

// ======================================================================
// Fused flash attention v4 (proven best): Q frags in registers;
// K AND V tiles double-buffered cp.async; 1 syncthreads per tile.
// ======================================================================
constexpr int FA_TSZ  = 64 * 36;
constexpr int FA_SMEM = 4 * FA_TSZ * 8;   // 73728

__global__ __launch_bounds__(128, 3)
void fa_kernel(const uint2* __restrict__ QPg, const float* __restrict__ Qf,
               const uint2* __restrict__ Kg, const uint2* __restrict__ Vt,
               float* __restrict__ Rg, int l)
{
    const int vt = blockIdx.x;
    const int bh = blockIdx.y;
    const int b = bh >> 3, h = bh & 7;
    const int t = threadIdx.x;
    const int lane = t & 31, warp = t >> 5;
    const int wm = warp * 16;
    const int fc = lane & 3, fg = lane >> 2;

    extern __shared__ uint2 smu[];
    uint2* Ks = smu;                      // [2][64][36]
    uint2* Vs = smu + 2 * FA_TSZ;         // [2][64][36]

    const float* qbase = Qf + ((size_t)(b * NV_ + vt * 64)) * HA_ + h * A_;
    const uint2* kbase = Kg + (size_t)(b * W_) * 1024 + (l * H_ + h) * 32;
    const uint2* vbase = Vt + ((size_t)b * 2048 + (l * H_ + h) * 64) * WP_;

    uint32_t qh[4][4], ql[4][4];
    {
        const uint2* qp = QPg + (size_t)(b * NV_ + vt * 64) * (HA_ / 2) + h * 32;
        const size_t r0 = (size_t)(wm + fg) * (HA_ / 2);
        const size_t r1 = (size_t)(wm + fg + 8) * (HA_ / 2);
#pragma unroll
        for (int kc = 0; kc < 4; kc++) {
            uint2 q0 = qp[r0 + kc * 8 + fc];
            uint2 q1 = qp[r1 + kc * 8 + fc];
            uint2 q2 = qp[r0 + kc * 8 + fc + 4];
            uint2 q3 = qp[r1 + kc * 8 + fc + 4];
            qh[kc][0] = q0.x; qh[kc][1] = q1.x; qh[kc][2] = q2.x; qh[kc][3] = q3.x;
            ql[kc][0] = q0.y; ql[kc][1] = q1.y; ql[kc][2] = q2.y; ql[kc][3] = q3.y;
        }
    }

    const int lr = t >> 1, lh = (t & 1) * 16;
    auto issueT = [&](int wt, int s) {
        const uint2* ksrc = kbase + (size_t)(wt * 64 + lr) * 1024 + lh;
        uint2* kdst = Ks + s * FA_TSZ + lr * 36 + lh;
        const uint2* vsrc = vbase + (size_t)lr * WP_ + wt * 32 + (t & 1) * 16;
        uint2* vdst = Vs + s * FA_TSZ + lr * 36 + (t & 1) * 16;
#pragma unroll
        for (int q = 0; q < 8; q++) {
            cp16(kdst + 2 * q, ksrc + 2 * q);
            cp16(vdst + 2 * q, vsrc + 2 * q);
        }
    };

    float O[8][4] = {};
    float s_m[2] = {-INFINITY, -INFINITY};
    float s_l[2] = {0.f, 0.f};

    const int ntiles = vt + 9;
    issueT(0, 0);
    CP_COMMIT();

    for (int wt = 0; wt < ntiles; wt++) {
        CP_WAIT0();
        __syncthreads();
        if (wt + 1 < ntiles) { issueT(wt + 1, (wt + 1) & 1); CP_COMMIT(); }

        const uint2* Kb = Ks + (wt & 1) * FA_TSZ;
        const uint2* Vb = Vs + (wt & 1) * FA_TSZ;

        float s[8][4] = {};
#pragma unroll
        for (int kc = 0; kc < 4; kc++) {
#pragma unroll
            for (int nt = 0; nt < 8; nt++) {
                int nc = nt * 8 + fg;
                uint2 k0 = Kb[nc * 36 + kc * 8 + fc];
                uint2 k1 = Kb[nc * 36 + kc * 8 + fc + 4];
                uint32_t bhv[2] = {k0.x, k1.x}, blv[2] = {k0.y, k1.y};
                mma_bf16(s[nt], qh[kc], bhv);
                mma_bf16(s[nt], qh[kc], blv);
                mma_bf16(s[nt], ql[kc], bhv);
            }
        }

        const bool mtile = (wt == vt + 8);
        float mx[2] = {-INFINITY, -INFINITY};
#pragma unroll
        for (int nt = 0; nt < 8; nt++)
#pragma unroll
            for (int c = 0; c < 4; c++) {
                float v = s[nt][c] * SCALE_;
                if (mtile) {
                    int wg = wt * 64 + nt * 8 + fc * 2 + (c & 1);
                    int vg = vt * 64 + wm + fg + (c >> 1) * 8;
                    if (wg >= NH_ + vg) v = -INFINITY;
                }
                s[nt][c] = v;
                mx[c >> 1] = fmaxf(mx[c >> 1], v);
            }
#pragma unroll
        for (int i = 0; i < 2; i++) {
            mx[i] = fmaxf(mx[i], __shfl_xor_sync(0xffffffffu, mx[i], 1));
            mx[i] = fmaxf(mx[i], __shfl_xor_sync(0xffffffffu, mx[i], 2));
        }

        float mnew[2], alpha[2], sum[2];
#pragma unroll
        for (int i = 0; i < 2; i++) {
            mnew[i] = fmaxf(s_m[i], mx[i]);
            alpha[i] = __expf(s_m[i] - mnew[i]);
            s_m[i] = mnew[i];
            sum[i] = 0.f;
        }
#pragma unroll
        for (int nt = 0; nt < 8; nt++)
#pragma unroll
            for (int c = 0; c < 4; c++) {
                float p = __expf(s[nt][c] - mnew[c >> 1]);
                s[nt][c] = p;
                sum[c >> 1] += p;
            }
#pragma unroll
        for (int i = 0; i < 2; i++) {
            sum[i] += __shfl_xor_sync(0xffffffffu, sum[i], 1);
            sum[i] += __shfl_xor_sync(0xffffffffu, sum[i], 2);
            s_l[i] = s_l[i] * alpha[i] + sum[i];
        }

#pragma unroll
        for (int ntj = 0; ntj < 8; ntj++)
#pragma unroll
            for (int c = 0; c < 4; c++)
                O[ntj][c] *= alpha[c >> 1];

#pragma unroll
        for (int kc = 0; kc < 4; kc++) {
            uint2 u;
            uint32_t ph[4], pl[4];
            u = split_bf16_pair(s[2 * kc][0], s[2 * kc][1]);         ph[0] = u.x; pl[0] = u.y;
            u = split_bf16_pair(s[2 * kc][2], s[2 * kc][3]);         ph[1] = u.x; pl[1] = u.y;
            u = split_bf16_pair(s[2 * kc + 1][0], s[2 * kc + 1][1]); ph[2] = u.x; pl[2] = u.y;
            u = split_bf16_pair(s[2 * kc + 1][2], s[2 * kc + 1][3]); ph[3] = u.x; pl[3] = u.y;
#pragma unroll
            for (int ntj = 0; ntj < 8; ntj++) {
                int nc = ntj * 8 + fg;
                uint2 v0 = Vb[nc * 36 + kc * 8 + fc];
                uint2 v1 = Vb[nc * 36 + kc * 8 + fc + 4];
                uint32_t bhv[2] = {v0.x, v1.x}, blv[2] = {v0.y, v1.y};
                mma_bf16(O[ntj], ph, bhv);
                mma_bf16(O[ntj], ph, blv);
                mma_bf16(O[ntj], pl, bhv);
            }
        }
    }

    float linv[2] = {1.f / s_l[0], 1.f / s_l[1]};
#pragma unroll
    for (int half = 0; half < 2; half++) {
        int row = wm + fg + half * 8;
        const float* arow = qbase + (size_t)row * HA_;
        float* orow = Rg + ((size_t)(b * NV_ + vt * 64 + row)) * HA_ + h * A_;
#pragma unroll
        for (int ntj = 0; ntj < 8; ntj++) {
            int j = ntj * 8 + fc * 2;
            float2 a = *(const float2*)(arow + j);
            float2 o;
            o.x = a.x + O[ntj][half * 2]     * linv[half];
            o.y = a.y + O[ntj][half * 2 + 1] * linv[half];
            *(float2*)(orow + j) = o;
        }
    }
}

// ---------------- layernorm: warp-per-row, shfl-only ----------------
__global__ void ln_kernel(const float* __restrict__ base, const float* __restrict__ delta,
                          const float* __restrict__ gamma, const float* __restrict__ beta,
                          float* __restrict__ out, uint2* __restrict__ outP) {
    const int warp = threadIdx.x >> 5, lane = threadIdx.x & 31;
    const int row = blockIdx.x * 8 + warp;
    const int c0 = lane * 16;
    const float* br = base + (size_t)row * HA_ + c0;
    float4 x[4];
#pragma unroll
    for (int q = 0; q < 4; q++) x[q] = *(const float4*)(br + q * 4);
    if (delta) {
        const float* dr = delta + (size_t)row * HA_ + c0;
#pragma unroll
        for (int q = 0; q < 4; q++) {
            float4 d = *(const float4*)(dr + q * 4);
            x[q].x += d.x; x[q].y += d.y; x[q].z += d.z; x[q].w += d.w;
        }
    }
    float sum = 0.f;
#pragma unroll
    for (int q = 0; q < 4; q++) sum += x[q].x + x[q].y + x[q].z + x[q].w;
#pragma unroll
    for (int o = 16; o > 0; o >>= 1) sum += __shfl_xor_sync(0xffffffffu, sum, o);
    float mean = sum * (1.f / HA_);
    float var = 0.f;
#pragma unroll
    for (int q = 0; q < 4; q++) {
        x[q].x -= mean; x[q].y -= mean; x[q].z -= mean; x[q].w -= mean;
        var += x[q].x * x[q].x + x[q].y * x[q].y + x[q].z * x[q].z + x[q].w * x[q].w;
    }
#pragma unroll
    for (int o = 16; o > 0; o >>= 1) var += __shfl_xor_sync(0xffffffffu, var, o);
    float inv = rsqrtf(var * (1.f / HA_) + EPS_);
    float* orow = out + (size_t)row * HA_ + c0;
    uint2* prow = outP + (size_t)row * (HA_ / 2) + (c0 >> 1);
#pragma unroll
    for (int q = 0; q < 4; q++) {
        float4 g = *(const float4*)(gamma + c0 + q * 4);
        float4 be = *(const float4*)(beta + c0 + q * 4);
        float4 o;
        o.x = g.x * (x[q].x * inv) + be.x;
        o.y = g.y * (x[q].y * inv) + be.y;
        o.z = g.z * (x[q].z * inv) + be.z;
        o.w = g.w * (x[q].w * inv) + be.w;
        *(float4*)(orow + q * 4) = o;
        prow[q * 2]     = split_bf16_pair(o.x, o.y);
        prow[q * 2 + 1] = split_bf16_pair(o.z, o.w);
    }
}

// ---------------- final loss reduction ----------------
__global__ void loss_kernel(const float* __restrict__ pu, float* __restrict__ out) {
    const int b = blockIdx.x;
    const int t = threadIdx.x;
    const int warp = t >> 5, lane = t & 31;
    const float LOG_R = logf((float)R_);
    float accum = 0.f;
    for (int v = 1 + warp; v < NV_; v += 8) {
        const float* lr = g_logits + ((size_t)(b * NV_ + v)) * R_;
        float lv[4];
        float m = -INFINITY;
#pragma unroll
        for (int i = 0; i < 4; i++) { lv[i] = lr[lane + i * 32]; m = fmaxf(m, lv[i]); }
#pragma unroll
        for (int o = 16; o > 0; o >>= 1) m = fmaxf(m, __shfl_xor_sync(0xffffffffu, m, o));
        float se = 0.f;
#pragma unroll
        for (int i = 0; i < 4; i++) se += expf(lv[i] - m);
#pragma unroll
        for (int o = 16; o > 0; o >>= 1) se += __shfl_xor_sync(0xffffffffu, se, o);
        if (lane == 0) {
            float lse = m + logf(se);
            int tgt = (int)floorf(pu[b * NV_ + v] * (float)R_);
            tgt = min(max(tgt, 0), R_ - 1);
            accum += lse - lr[tgt] - LOG_R;
        }
    }
    __shared__ float red[8];
    if (lane == 0) red[warp] = accum;
    __syncthreads();
    if (t == 0) {
        float s = 0.f;
#pragma unroll
        for (int i = 0; i < 8; i++) s += red[i];
        out[b] = s;
    }
}

// ---------------- host launch ----------------
template <typename T>
static T* sym_addr(const void* sym) {
    void* p = nullptr;
    cudaGetSymbolAddress(&p, sym);
    return (T*)p;
}

extern "C" void kernel_launch(void* const* d_in, const int* in_sizes, int n_in,
                              void* d_out, int out_size) {
    (void)in_sizes; (void)n_in; (void)out_size;
    const float* hist  = (const float*)d_in[0];
    const float* hu    = (const float*)d_in[1];
    const float* pred  = (const float*)d_in[2];
    const float* pu    = (const float*)d_in[3];
    const float* ds_w  = (const float*)d_in[4];
    const float* ds_b  = (const float*)d_in[5];
    const float* key_w = (const float*)d_in[6];
    const float* key_b = (const float*)d_in[7];
    const float* val_w = (const float*)d_in[8];
    const float* val_b = (const float*)d_in[9];
    const float* ln1_g = (const float*)d_in[10];
    const float* ln1_b = (const float*)d_in[11];
    const float* ln2_g = (const float*)d_in[12];
    const float* ln2_b = (const float*)d_in[13];
    const float* ff_w1 = (const float*)d_in[14];
    const float* ff_b1 = (const float*)d_in[15];
    const float* ff_w2 = (const float*)d_in[16];
    const float* ff_b2 = (const float*)d_in[17];
    const float* ff_w3 = (const float*)d_in[18];
    const float* ff_b3 = (const float*)d_in[19];
    const float* de_w  = (const float*)d_in[20];
    const float* de_b  = (const float*)d_in[21];
    float* out = (float*)d_out;

    uint2* kiP   = sym_addr<uint2>(g_kiP);
    uint2* kvwP  = sym_addr<uint2>(g_kvwP);
    float* kvb   = sym_addr<float>(g_kvb);
    uint2* predP = sym_addr<uint2>(g_predP);
    uint2* dswP  = sym_addr<uint2>(g_dswP);
    uint2* dewP  = sym_addr<uint2>(g_dewP);
    uint2* ffw1P = sym_addr<uint2>(g_ffw1P);
    uint2* ffw2P = sym_addr<uint2>(g_ffw2P);
    uint2* ffw3P = sym_addr<uint2>(g_ffw3P);
    uint2* kP    = sym_addr<uint2>(g_kP);
    uint2* vT    = sym_addr<uint2>(g_vT);
    float* att   = sym_addr<float>(g_att);
    uint2* attP  = sym_addr<uint2>(g_attP);
    float* res   = sym_addr<float>(g_res);
    uint2* ff1P  = sym_addr<uint2>(g_ff1P);
    uint2* ff2P  = sym_addr<uint2>(g_ff2P);
    float* logit = sym_addr<float>(g_logits);

    const int SM64  = 3 * (64 * 12 + 8 * 68) * 8;
    const int SM128 = 3 * (128 * 12 + 8 * 68) * 8;

    cudaFuncSetAttribute(fa_kernel, cudaFuncAttributeMaxDynamicSharedMemorySize, FA_SMEM);
    cudaFuncSetAttribute(gemm_tc<64, false, false, false>, cudaFuncAttributeMaxDynamicSharedMemorySize, SM64);
    cudaFuncSetAttribute(gemm_tc<64, true, true, false>, cudaFuncAttributeMaxDynamicSharedMemorySize, SM64);
    cudaFuncSetAttribute(gemm_tc<128, false, true, true>, cudaFuncAttributeMaxDynamicSharedMemorySize, SM128);

    const int BNV = B_ * NV_;
    const int BW  = B_ * W_;

    // ---- merged prep (1 launch) ----
    prep_all<<<(PP_TOTAL + 255) / 256, 256>>>(hist, hu, pred, pu, key_w, val_w, key_b, val_b,
                                              ds_w, de_w, ff_w1, ff_w2, ff_w3);

    // ---- ds: att = pred @ ds_w + b  (dual output: f32 + packed attP)
    gemm_tc<64, false, false, false><<<dim3(HA_ / 64, BNV / 64), 128, SM64>>>(
        predP, dswP, ds_b, att, attP, HA_ / 2, 16, D_ / 2, HA_, HA_);
    // ---- keys|vals combined; keys -> g_kP packed, vals -> g_vT transposed
    gemm_tc<128, false, true, true><<<dim3(4096 / 64, BW / 128), 128, SM128>>>(
        kiP, kvwP, kvb, kP, vT, 0, 17, KI_KP_, 4096, 1024);

    // ---- layers ----
    for (int l = 0; l < L_; l++) {
        fa_kernel<<<dim3(NV_ / 64, B_ * H_), 128, FA_SMEM>>>(attP, att, kP, vT, res, l);
        ln_kernel<<<BNV / 8, 256>>>(res, nullptr, ln1_g + l * HA_, ln1_b + l * HA_, att, attP);
        gemm_tc<64, true, true, false><<<dim3(M_ / 64, BNV / 64), 128, SM64>>>(
            attP, ffw1P + (size_t)l * (HA_ / 2) * M_, ff_b1 + l * M_, ff1P, nullptr, 0,
            32, HA_ / 2, M_, M_ / 2);
        gemm_tc<64, true, true, false><<<dim3(M_ / 64, BNV / 64), 128, SM64>>>(
            ff1P, ffw2P + (size_t)l * (M_ / 2) * M_, ff_b2 + l * M_, ff2P, nullptr, 0,
            32, M_ / 2, M_, M_ / 2);
        gemm_tc<64, false, false, false><<<dim3(HA_ / 64, BNV / 64), 128, SM64>>>(
            ff2P, ffw3P + (size_t)l * (M_ / 2) * HA_, ff_b3 + l * HA_, res, nullptr, 0,
            32, M_ / 2, HA_, HA_);
        ln_kernel<<<BNV / 8, 256>>>(att, res, ln2_g + l * HA_, ln2_b + l * HA_, att, attP);
    }
    // ---- logits + loss ----
    gemm_tc<64, false, false, false><<<dim3(R_ / 64, BNV / 64), 128, SM64>>>(
        attP, dewP, de_b, logit, nullptr, 0, 32, HA_ / 2, R_, R_);
    loss_kernel<<<B_, 256>>>(pu, out);
}